// round 15
// baseline (speedup 1.0000x reference)
#include <cuda_runtime.h>
#include <cuda_bf16.h>
#include <cuda_fp16.h>
#include <math.h>
#include <stdint.h>

#define NNODE 100000
#define NPAD  100096          // 782 * 128
#define NEDGE 3200000
#define NFEAT 512
#define HID   256
#define NCLS  64
#define NLAY  8
#define GRID_M 782            // NPAD / 128
#define KTOT  ((NLAY + 1) * HID)   // 2304
#define KCUT1 1280                 // slabs 0..4
#define KCUT2 2048                 // slabs 5..7

// ---------------- static device scratch -------------------------------------
__device__ __align__(16) __half    g_Xbuf0[(size_t)NPAD * HID];  // H (immutable after init)
__device__ __align__(16) __half    g_Xbuf1[(size_t)NPAD * HID];  // ping
__device__ __align__(16) __half    g_Xbuf2[(size_t)NPAD * HID];  // pong
__device__ __align__(16) __half    g_AXall[(size_t)NLAY * NPAD * HID]; // AX_1..8 (slab l-1)
__device__ __align__(16) float     g_Yh0[(size_t)NPAD * NCLS];   // partial Y
__device__ __half g_Wt[HID * NFEAT];               // Winit^T fp16 [n][k]
__device__ __half g_PtAll[NCLS * KTOT];            // fp16 [n][slab*256+k]
__device__ int   g_rowptr[NNODE + 1];
__device__ int   g_cursor[NNODE];
__device__ int2  g_cw[NEDGE];                      // (col, weight bits)
__device__ int   g_bsum[128];
__device__ int   g_boff[128];

static inline int cdiv(int a, int b) { return (a + b - 1) / b; }

__device__ __forceinline__ uint32_t smem_to_u32(const void* p) {
    uint32_t a;
    asm("{ .reg .u64 t; cvta.to.shared.u64 t, %1; cvt.u32.u64 %0, t; }" : "=r"(a) : "l"(p));
    return a;
}

// ---------------- CSR build --------------------------------------------------
__global__ __launch_bounds__(256)
void hist_kernel(const int* __restrict__ erow) {
    int e4 = (blockIdx.x * blockDim.x + threadIdx.x) * 4;
    if (e4 < NEDGE) {
        int4 r = *reinterpret_cast<const int4*>(erow + e4);
        atomicAdd(&g_cursor[r.x], 1);
        atomicAdd(&g_cursor[r.y], 1);
        atomicAdd(&g_cursor[r.z], 1);
        atomicAdd(&g_cursor[r.w], 1);
    }
}
__global__ __launch_bounds__(1024)
void scanA_kernel() {
    __shared__ int sd[1024];
    const int tid = threadIdx.x;
    const int i = blockIdx.x * 1024 + tid;
    int v = (i < NNODE) ? g_cursor[i] : 0;
    sd[tid] = v;
    __syncthreads();
    #pragma unroll
    for (int off = 1; off < 1024; off <<= 1) {
        int t = (tid >= off) ? sd[tid - off] : 0;
        __syncthreads();
        sd[tid] += t;
        __syncthreads();
    }
    if (i < NNODE) g_rowptr[i] = sd[tid] - v;
    if (tid == 1023) g_bsum[blockIdx.x] = sd[1023];
}
__global__ __launch_bounds__(128)
void scanB_kernel(int nblk) {
    __shared__ int sd[128];
    const int tid = threadIdx.x;
    int v = (tid < nblk) ? g_bsum[tid] : 0;
    sd[tid] = v;
    __syncthreads();
    #pragma unroll
    for (int off = 1; off < 128; off <<= 1) {
        int t = (tid >= off) ? sd[tid - off] : 0;
        __syncthreads();
        sd[tid] += t;
        __syncthreads();
    }
    if (tid < nblk) g_boff[tid] = sd[tid] - v;
}
__global__ void scanC_kernel() {
    int i = blockIdx.x * blockDim.x + threadIdx.x;
    if (i < NNODE) {
        int r = g_rowptr[i] + g_boff[i >> 10];
        g_rowptr[i] = r;
        g_cursor[i] = r;
    }
    if (i == 0) g_rowptr[NNODE] = NEDGE;
}
__global__ __launch_bounds__(256)
void scatter_kernel(const int* __restrict__ erow,
                    const int* __restrict__ ecol,
                    const float* __restrict__ ew) {
    int e4 = (blockIdx.x * blockDim.x + threadIdx.x) * 4;
    if (e4 < NEDGE) {
        int4   r = *reinterpret_cast<const int4*>(erow + e4);
        int4   c = *reinterpret_cast<const int4*>(ecol + e4);
        float4 w = *reinterpret_cast<const float4*>(ew + e4);
        int p0 = atomicAdd(&g_cursor[r.x], 1);
        int p1 = atomicAdd(&g_cursor[r.y], 1);
        int p2 = atomicAdd(&g_cursor[r.z], 1);
        int p3 = atomicAdd(&g_cursor[r.w], 1);
        g_cw[p0] = make_int2(c.x, __float_as_int(w.x));
        g_cw[p1] = make_int2(c.y, __float_as_int(w.y));
        g_cw[p2] = make_int2(c.z, __float_as_int(w.z));
        g_cw[p3] = make_int2(c.w, __float_as_int(w.w));
    }
}

// ---------------- weight prep -------------------------------------------------
__global__ void prepWt_kernel(const float* __restrict__ Winit) {
    int i = blockIdx.x * blockDim.x + threadIdx.x;
    if (i < HID * NFEAT) {
        int n = i >> 9, k = i & 511;
        g_Wt[i] = __float2half(Winit[(size_t)k * HID + n]);
    }
}
__global__ void prepWsT_kernel(const float* __restrict__ Wsort) {
    int i = blockIdx.x * blockDim.x + threadIdx.x;
    if (i < NCLS * HID) {
        int n = i >> 8, k = i & 255;
        g_PtAll[(size_t)n * KTOT + k] = __float2half(Wsort[(size_t)k * NCLS + n]);
    }
}
// 32 blocks: block = l*4 + c (one 64-row k-chunk of layer l)
__global__ void prepP_kernel(const float* __restrict__ Ws, const float* __restrict__ Wsort) {
    extern __shared__ float psm[];
    float* sWs = psm;                 // [j][n] 256x64
    float* sW  = psm + HID * NCLS;    // [r][j] 64x256
    const int l = blockIdx.x >> 2;
    const int c = blockIdx.x & 3;
    const int tid = threadIdx.x;
    const float beta = 0.5f / (float)(l + 1);

    for (int i = tid; i < HID * NCLS; i += 256) sWs[i] = Wsort[i];
    for (int i = tid; i < 64 * HID; i += 256)
        sW[i] = Ws[(size_t)l * HID * HID + (size_t)c * 64 * HID + i];
    __syncthreads();

    const int r  = tid & 63;
    const int ng = tid >> 6;
    const int k = c * 64 + r;
    float acc[16];
    #pragma unroll
    for (int j = 0; j < 16; j++) acc[j] = 0.f;
    for (int j2 = 0; j2 < HID; j2++) {
        float w = sW[r * HID + j2];
        #pragma unroll
        for (int j = 0; j < 16; j++)
            acc[j] = fmaf(w, sWs[j2 * NCLS + ng * 16 + j], acc[j]);
    }
    #pragma unroll
    for (int j = 0; j < 16; j++) {
        int n = ng * 16 + j;
        float p = (1.f - beta) * sWs[k * NCLS + n] + beta * acc[j];
        g_PtAll[(size_t)n * KTOT + (size_t)(l + 1) * HID + k] = __float2half(p);
    }
}

// ---------------- HMMA helpers -------------------------------------------------
#define APITCH 40

__device__ __forceinline__ void ldm_x4(uint32_t* d, uint32_t addr) {
    asm volatile("ldmatrix.sync.aligned.m8n8.x4.shared.b16 {%0,%1,%2,%3}, [%4];"
                 : "=r"(d[0]), "=r"(d[1]), "=r"(d[2]), "=r"(d[3]) : "r"(addr));
}
__device__ __forceinline__ void mma16816fp(float* c, const uint32_t* a, const uint32_t* b) {
    asm volatile(
        "mma.sync.aligned.m16n8k16.row.col.f32.f16.f16.f32 "
        "{%0,%1,%2,%3}, {%4,%5,%6,%7}, {%8,%9}, {%0,%1,%2,%3};"
        : "+f"(c[0]), "+f"(c[1]), "+f"(c[2]), "+f"(c[3])
        : "r"(a[0]), "r"(a[1]), "r"(a[2]), "r"(a[3]), "r"(b[0]), "r"(b[1]));
}

// ---------------- init GEMM (software-pipelined): H = X @ Winit + b ----------
// grid = (2, 782): column index fastest -> the two col-blocks of the same rows
// are placement-adjacent and share A reads via L2.
#define NCHUNK (NFEAT / 32)   // 16
__global__ __launch_bounds__(256, 2)
void gemm_init_kernel(const float* __restrict__ X,
                      const float* __restrict__ bias,
                      __half* __restrict__ Hout)
{
    __shared__ __align__(16) __half sA[2][128 * APITCH];
    __shared__ __align__(16) __half sB[2][128 * APITCH];

    const int tid = threadIdx.x;
    const int wid = tid >> 5, lid = tid & 31;
    const int row0 = blockIdx.y * 128;
    const int col0 = blockIdx.x * 128;
    const int mwr = (wid >> 1) * 32;
    const int nwb = (wid & 1) * 64;

    const uint32_t sAb = smem_to_u32(sA);
    const uint32_t sBb = smem_to_u32(sB);
    const uint32_t stageBytes = 128 * APITCH * 2;

    const int ar[4] = { (0 * 256 + tid) >> 3, (1 * 256 + tid) >> 3,
                        (2 * 256 + tid) >> 3, (3 * 256 + tid) >> 3 };
    const int as = tid & 7;
    const int br[2] = { (0 * 256 + tid) >> 2, (1 * 256 + tid) >> 2 };
    const int bs = tid & 3;

    float4 fA[4];
    uint4  uB[2];

    auto loadG = [&](int ch) {
        const int kk = ch * 32;
        #pragma unroll
        for (int i = 0; i < 4; i++) {
            int grow = row0 + ar[i];
            fA[i] = (grow < NNODE)
                ? *reinterpret_cast<const float4*>(X + (size_t)grow * NFEAT + kk + as * 4)
                : make_float4(0.f, 0.f, 0.f, 0.f);
        }
        #pragma unroll
        for (int i = 0; i < 2; i++)
            uB[i] = *reinterpret_cast<const uint4*>(
                g_Wt + (size_t)(col0 + br[i]) * NFEAT + kk + bs * 8);
    };
    auto storeS = [&](int st) {
        #pragma unroll
        for (int i = 0; i < 4; i++) {
            __half2 h01 = __floats2half2_rn(fA[i].x, fA[i].y);
            __half2 h23 = __floats2half2_rn(fA[i].z, fA[i].w);
            *reinterpret_cast<uint2*>(&sA[st][ar[i] * APITCH + as * 4]) =
                make_uint2(*reinterpret_cast<uint32_t*>(&h01), *reinterpret_cast<uint32_t*>(&h23));
        }
        #pragma unroll
        for (int i = 0; i < 2; i++)
            *reinterpret_cast<uint4*>(&sB[st][br[i] * APITCH + bs * 8]) = uB[i];
    };

    float acc[2][8][4];
    #pragma unroll
    for (int i = 0; i < 2; i++)
        #pragma unroll
        for (int j = 0; j < 8; j++)
            #pragma unroll
            for (int q = 0; q < 4; q++) acc[i][j][q] = 0.f;

    loadG(0);
    storeS(0);
    __syncthreads();

    for (int ch = 0; ch < NCHUNK; ch++) {
        const int cur = ch & 1;
        if (ch + 1 < NCHUNK) loadG(ch + 1);

        #pragma unroll
        for (int ks = 0; ks < 2; ks++) {
            uint32_t a[2][4], b[8][2];
            #pragma unroll
            for (int mi = 0; mi < 2; mi++) {
                uint32_t off = cur * stageBytes +
                    (uint32_t)((mwr + mi * 16 + (lid & 15)) * APITCH
                               + ks * 16 + (lid >> 4) * 8) * 2;
                ldm_x4(a[mi], sAb + off);
            }
            #pragma unroll
            for (int nj = 0; nj < 4; nj++) {
                uint32_t off = cur * stageBytes +
                    (uint32_t)((nwb + nj * 16 + (lid & 7) + ((lid >> 4) & 1) * 8) * APITCH
                               + ks * 16 + ((lid >> 3) & 1) * 8) * 2;
                uint32_t t0[4];
                ldm_x4(t0, sBb + off);
                b[2 * nj][0] = t0[0]; b[2 * nj][1] = t0[1];
                b[2 * nj + 1][0] = t0[2]; b[2 * nj + 1][1] = t0[3];
            }
            #pragma unroll
            for (int mi = 0; mi < 2; mi++)
                #pragma unroll
                for (int nj = 0; nj < 8; nj++)
                    mma16816fp(acc[mi][nj], a[mi], b[nj]);
        }
        __syncthreads();
        if (ch + 1 < NCHUNK) {
            storeS(cur ^ 1);
            __syncthreads();
        }
    }

    const int g = lid >> 2, tg = lid & 3;
    #pragma unroll
    for (int mi = 0; mi < 2; mi++)
        #pragma unroll
        for (int half = 0; half < 2; half++) {
            int row = row0 + mwr + mi * 16 + g + half * 8;
            size_t rb = (size_t)row * HID;
            #pragma unroll
            for (int nj = 0; nj < 8; nj++) {
                int col = nwb + col0 + nj * 8 + tg * 2;
                float v0 = acc[mi][nj][half * 2 + 0] + bias[col];
                float v1 = acc[mi][nj][half * 2 + 1] + bias[col + 1];
                *reinterpret_cast<__half2*>(Hout + rb + col) = __floats2half2_rn(v0, v1);
            }
        }
}

// ---- partial GEMM over K range. slab 0 = H (param), slabs 1..8 = g_AXall.
//      MODE 0: Yh = acc; 1: Yh += acc; 2: out = log_softmax(acc + Yh + bias)
template<int KBEG, int KEND, int MODE>
__global__ __launch_bounds__(128, 4)
void gemm_part_kernel(const __half* __restrict__ H,
                      const float* __restrict__ bias,
                      float* __restrict__ Yh, float* __restrict__ out)
{
    __shared__ __align__(16) __half sA[128 * APITCH];
    __shared__ __align__(16) __half sB[64 * APITCH];

    const int tid = threadIdx.x;
    const int wid = tid >> 5, lid = tid & 31;
    const int row0 = blockIdx.x * 128;
    const int mwr = wid * 32;

    const uint32_t sAb = smem_to_u32(sA);
    const uint32_t sBb = smem_to_u32(sB);

    float acc[2][8][4];
    #pragma unroll
    for (int i = 0; i < 2; i++)
        #pragma unroll
        for (int j = 0; j < 8; j++)
            #pragma unroll
            for (int q = 0; q < 4; q++) acc[i][j][q] = 0.f;

    for (int kk = KBEG; kk < KEND; kk += 32) {
        const int slab = kk >> 8;
        const __half* Ap = (slab == 0) ? H : (g_AXall + (size_t)(slab - 1) * NPAD * HID);
        const int inner = kk & 255;
        #pragma unroll
        for (int i = 0; i < 4; i++) {
            int seg = i * 128 + tid;
            int r = seg >> 2, s = seg & 3;
            uint4 p = __ldcs(reinterpret_cast<const uint4*>(
                Ap + (size_t)(row0 + r) * HID + inner + s * 8));
            *reinterpret_cast<uint4*>(sA + r * APITCH + s * 8) = p;
        }
        #pragma unroll
        for (int i = 0; i < 2; i++) {
            int seg = i * 128 + tid;
            int r = seg >> 2, s = seg & 3;
            uint4 p = *reinterpret_cast<const uint4*>(g_PtAll + (size_t)r * KTOT + kk + s * 8);
            *reinterpret_cast<uint4*>(sB + r * APITCH + s * 8) = p;
        }
        __syncthreads();

        #pragma unroll
        for (int ks = 0; ks < 2; ks++) {
            uint32_t a[2][4], b[8][2];
            #pragma unroll
            for (int mi = 0; mi < 2; mi++) {
                uint32_t off = (uint32_t)((mwr + mi * 16 + (lid & 15)) * APITCH
                                          + ks * 16 + (lid >> 4) * 8) * 2;
                ldm_x4(a[mi], sAb + off);
            }
            #pragma unroll
            for (int nj = 0; nj < 4; nj++) {
                uint32_t off = (uint32_t)((nj * 16 + (lid & 7) + ((lid >> 4) & 1) * 8) * APITCH
                                          + ks * 16 + ((lid >> 3) & 1) * 8) * 2;
                uint32_t t0[4];
                ldm_x4(t0, sBb + off);
                b[2 * nj][0] = t0[0]; b[2 * nj][1] = t0[1];
                b[2 * nj + 1][0] = t0[2]; b[2 * nj + 1][1] = t0[3];
            }
            #pragma unroll
            for (int mi = 0; mi < 2; mi++)
                #pragma unroll
                for (int nj = 0; nj < 8; nj++)
                    mma16816fp(acc[mi][nj], a[mi], b[nj]);
        }
        __syncthreads();
    }

    const int g = lid >> 2, tg = lid & 3;
    if (MODE == 0) {
        #pragma unroll
        for (int mi = 0; mi < 2; mi++)
            #pragma unroll
            for (int half = 0; half < 2; half++) {
                int row = row0 + mwr + mi * 16 + g + half * 8;
                size_t rb = (size_t)row * NCLS;
                #pragma unroll
                for (int nj = 0; nj < 8; nj++) {
                    int col = nj * 8 + tg * 2;
                    *reinterpret_cast<float2*>(Yh + rb + col) =
                        make_float2(acc[mi][nj][half * 2 + 0], acc[mi][nj][half * 2 + 1]);
                }
            }
    } else if (MODE == 1) {
        #pragma unroll
        for (int mi = 0; mi < 2; mi++)
            #pragma unroll
            for (int half = 0; half < 2; half++) {
                int row = row0 + mwr + mi * 16 + g + half * 8;
                size_t rb = (size_t)row * NCLS;
                #pragma unroll
                for (int nj = 0; nj < 8; nj++) {
                    int col = nj * 8 + tg * 2;
                    float2 p = *reinterpret_cast<const float2*>(Yh + rb + col);
                    p.x += acc[mi][nj][half * 2 + 0];
                    p.y += acc[mi][nj][half * 2 + 1];
                    *reinterpret_cast<float2*>(Yh + rb + col) = p;
                }
            }
    } else {
        #pragma unroll
        for (int mi = 0; mi < 2; mi++)
            #pragma unroll
            for (int half = 0; half < 2; half++) {
                int row = row0 + mwr + mi * 16 + g + half * 8;
                size_t rb = (size_t)row * NCLS;
                float v[16];
                float m = -INFINITY;
                #pragma unroll
                for (int nj = 0; nj < 8; nj++) {
                    int col = nj * 8 + tg * 2;
                    float2 p = *reinterpret_cast<const float2*>(Yh + rb + col);
                    v[2 * nj]     = acc[mi][nj][half * 2 + 0] + p.x + bias[col];
                    v[2 * nj + 1] = acc[mi][nj][half * 2 + 1] + p.y + bias[col + 1];
                    m = fmaxf(m, fmaxf(v[2 * nj], v[2 * nj + 1]));
                }
                m = fmaxf(m, __shfl_xor_sync(0xffffffffu, m, 1));
                m = fmaxf(m, __shfl_xor_sync(0xffffffffu, m, 2));
                float s = 0.f;
                #pragma unroll
                for (int j = 0; j < 16; j++) s += expf(v[j] - m);
                s += __shfl_xor_sync(0xffffffffu, s, 1);
                s += __shfl_xor_sync(0xffffffffu, s, 2);
                float lse = m + logf(s);
                if (row < NNODE) {
                    #pragma unroll
                    for (int nj = 0; nj < 8; nj++) {
                        int col = nj * 8 + tg * 2;
                        *reinterpret_cast<float2*>(out + rb + col) =
                            make_float2(v[2 * nj] - lse, v[2 * nj + 1] - lse);
                    }
                }
            }
    }
}

// ---------------- fused SpMM + X-update (fp16 X, warp per row, 8-unroll) ------
__device__ __forceinline__ void acc8(float* v, float w, const uint4& x) {
    const __half2* h = reinterpret_cast<const __half2*>(&x);
    #pragma unroll
    for (int j = 0; j < 4; j++) {
        float2 f = __half22float2(h[j]);
        v[2 * j]     = fmaf(w, f.x, v[2 * j]);
        v[2 * j + 1] = fmaf(w, f.y, v[2 * j + 1]);
    }
}

__global__ __launch_bounds__(256)
void spmm_fused_kernel(const __half* __restrict__ Xc, __half* __restrict__ Xn,
                       __half* __restrict__ AXs,
                       const float* __restrict__ gammas, int l)
{
    const int wid  = threadIdx.x >> 5;
    const int lane = threadIdx.x & 31;
    const int row  = blockIdx.x * 8 + wid;
    const int fb   = lane * 8;
    int i = g_rowptr[row];
    const int e = g_rowptr[row + 1];

    float v[8];
    #pragma unroll
    for (int j = 0; j < 8; j++) v[j] = 0.f;

    for (; i + 8 <= e; i += 8) {
        int2 c0 = __ldcs(&g_cw[i + 0]);
        int2 c1 = __ldcs(&g_cw[i + 1]);
        int2 c2 = __ldcs(&g_cw[i + 2]);
        int2 c3 = __ldcs(&g_cw[i + 3]);
        int2 c4 = __ldcs(&g_cw[i + 4]);
        int2 c5 = __ldcs(&g_cw[i + 5]);
        int2 c6 = __ldcs(&g_cw[i + 6]);
        int2 c7 = __ldcs(&g_cw[i + 7]);
        uint4 x0 = __ldg(reinterpret_cast<const uint4*>(Xc + (size_t)c0.x * HID + fb));
        uint4 x1 = __ldg(reinterpret_cast<const uint4*>(Xc + (size_t)c1.x * HID + fb));
        uint4 x2 = __ldg(reinterpret_cast<const uint4*>(Xc + (size_t)c2.x * HID + fb));
        uint4 x3 = __ldg(reinterpret_cast<const uint4*>(Xc + (size_t)c3.x * HID + fb));
        uint4 x4 = __ldg(reinterpret_cast<const uint4*>(Xc + (size_t)c4.x * HID + fb));
        uint4 x5 = __ldg(reinterpret_cast<const uint4*>(Xc + (size_t)c5.x * HID + fb));
        uint4 x6 = __ldg(reinterpret_cast<const uint4*>(Xc + (size_t)c6.x * HID + fb));
        uint4 x7 = __ldg(reinterpret_cast<const uint4*>(Xc + (size_t)c7.x * HID + fb));
        acc8(v, __int_as_float(c0.y), x0);
        acc8(v, __int_as_float(c1.y), x1);
        acc8(v, __int_as_float(c2.y), x2);
        acc8(v, __int_as_float(c3.y), x3);
        acc8(v, __int_as_float(c4.y), x4);
        acc8(v, __int_as_float(c5.y), x5);
        acc8(v, __int_as_float(c6.y), x6);
        acc8(v, __int_as_float(c7.y), x7);
    }
    for (; i + 2 <= e; i += 2) {
        int2 c0 = __ldcs(&g_cw[i + 0]);
        int2 c1 = __ldcs(&g_cw[i + 1]);
        uint4 x0 = __ldg(reinterpret_cast<const uint4*>(Xc + (size_t)c0.x * HID + fb));
        uint4 x1 = __ldg(reinterpret_cast<const uint4*>(Xc + (size_t)c1.x * HID + fb));
        acc8(v, __int_as_float(c0.y), x0);
        acc8(v, __int_as_float(c1.y), x1);
    }
    if (i < e) {
        int2 c0 = __ldcs(&g_cw[i]);
        uint4 x0 = __ldg(reinterpret_cast<const uint4*>(Xc + (size_t)c0.x * HID + fb));
        acc8(v, __int_as_float(c0.y), x0);
    }

    const size_t idx = (size_t)row * HID + fb;
    const float g = gammas[l];
    uint4 xc4 = *reinterpret_cast<const uint4*>(Xc + idx);
    const __half2* xch = reinterpret_cast<const __half2*>(&xc4);
    uint4 xn4, ax4;
    __half2* xnh = reinterpret_cast<__half2*>(&xn4);
    __half2* axh = reinterpret_cast<__half2*>(&ax4);
    #pragma unroll
    for (int j = 0; j < 4; j++) {
        float2 f = __half22float2(xch[j]);
        axh[j] = __floats2half2_rn(v[2 * j], v[2 * j + 1]);
        xnh[j] = __floats2half2_rn(g * (f.x - v[2 * j]), g * (f.y - v[2 * j + 1]));
    }
    *reinterpret_cast<uint4*>(Xn + idx) = xn4;                       // stay L2-resident
    __stcs(reinterpret_cast<uint4*>(AXs + idx), ax4);                // consumed later
}

// ---------------- launch ------------------------------------------------------
extern "C" void kernel_launch(void* const* d_in, const int* in_sizes, int n_in,
                              void* d_out, int out_size)
{
    const float* X      = (const float*)d_in[0];
    const int*   erow   = (const int*)  d_in[1];
    const int*   ecol   = (const int*)  d_in[2];
    const float* ew     = (const float*)d_in[3];
    const float* Winit  = (const float*)d_in[4];
    const float* binit  = (const float*)d_in[5];
    const float* gammas = (const float*)d_in[6];
    const float* Ws     = (const float*)d_in[7];
    const float* Wsort  = (const float*)d_in[8];
    const float* bsort  = (const float*)d_in[9];
    float* out = (float*)d_out;

    __half *pX0, *pX1, *pX2, *pAXall;
    float *pYh0;
    int *pCursor;
    cudaGetSymbolAddress((void**)&pX0,     g_Xbuf0);
    cudaGetSymbolAddress((void**)&pX1,     g_Xbuf1);
    cudaGetSymbolAddress((void**)&pX2,     g_Xbuf2);
    cudaGetSymbolAddress((void**)&pAXall,  g_AXall);
    cudaGetSymbolAddress((void**)&pYh0,    g_Yh0);
    cudaGetSymbolAddress((void**)&pCursor, g_cursor);

    static int inited = 0;
    static cudaStream_t s2;
    static cudaEvent_t evFork, evJoin, evSlab4, evSlab7, evP1;
    if (!inited) {
        cudaFuncSetAttribute(prepP_kernel,
                             cudaFuncAttributeMaxDynamicSharedMemorySize, 131072);
        cudaStreamCreateWithFlags(&s2, cudaStreamNonBlocking);
        cudaEventCreateWithFlags(&evFork,  cudaEventDisableTiming);
        cudaEventCreateWithFlags(&evJoin,  cudaEventDisableTiming);
        cudaEventCreateWithFlags(&evSlab4, cudaEventDisableTiming);
        cudaEventCreateWithFlags(&evSlab7, cudaEventDisableTiming);
        cudaEventCreateWithFlags(&evP1,    cudaEventDisableTiming);
        inited = 1;
    }

    // ---- fork ----
    cudaEventRecord(evFork, 0);
    cudaStreamWaitEvent(s2, evFork, 0);

    // s2: P-weight prep + CSR build (vectorized)
    prepWsT_kernel<<<cdiv(NCLS * HID, 256), 256, 0, s2>>>(Wsort);
    prepP_kernel<<<NLAY * 4, 256, 131072, s2>>>(Ws, Wsort);
    cudaMemsetAsync(pCursor, 0, NNODE * sizeof(int), s2);
    hist_kernel<<<cdiv(NEDGE / 4, 256), 256, 0, s2>>>(erow);
    scanA_kernel<<<cdiv(NNODE, 1024), 1024, 0, s2>>>();
    scanB_kernel<<<1, 128, 0, s2>>>(cdiv(NNODE, 1024));
    scanC_kernel<<<cdiv(NNODE, 256), 256, 0, s2>>>();
    scatter_kernel<<<cdiv(NEDGE / 4, 256), 256, 0, s2>>>(erow, ecol, ew);
    cudaEventRecord(evJoin, s2);

    // main: Wt prep + init GEMM (H -> Xbuf0 only; kept immutable = slab 0)
    prepWt_kernel<<<cdiv(HID * NFEAT, 256), 256>>>(Winit);
    dim3 ig(2, GRID_M);   // column index fastest -> A reads shared via L2
    gemm_init_kernel<<<ig, 256>>>(X, binit, pX0);

    // ---- join: SpMM chain needs CSR + H ----
    cudaStreamWaitEvent(0, evJoin, 0);

    // X rotation: layer 0 reads X0 -> X1; then X1<->X2 alternate.
    __half* xin[NLAY]  = { pX0, pX1, pX2, pX1, pX2, pX1, pX2, pX1 };
    __half* xout[NLAY] = { pX1, pX2, pX1, pX2, pX1, pX2, pX1, pX2 };

    for (int l = 0; l < 4; l++) {
        spmm_fused_kernel<<<NNODE / 8, 256>>>(
            xin[l], xout[l], pAXall + (size_t)l * NPAD * HID, gammas, l);
    }
    cudaEventRecord(evSlab4, 0);

    // s2: slabs 0..4 GEMM overlapped with SpMM layers 4..6
    cudaStreamWaitEvent(s2, evSlab4, 0);
    gemm_part_kernel<0, KCUT1, 0><<<GRID_M, 128, 0, s2>>>(pX0, nullptr, pYh0, nullptr);

    for (int l = 4; l < 7; l++) {
        spmm_fused_kernel<<<NNODE / 8, 256>>>(
            xin[l], xout[l], pAXall + (size_t)l * NPAD * HID, gammas, l);
    }
    cudaEventRecord(evSlab7, 0);

    // s2: slabs 5..7 GEMM (accumulate) overlapped with SpMM layer 7
    cudaStreamWaitEvent(s2, evSlab7, 0);
    gemm_part_kernel<KCUT1, KCUT2, 1><<<GRID_M, 128, 0, s2>>>(pX0, nullptr, pYh0, nullptr);
    cudaEventRecord(evP1, s2);

    // main: last SpMM layer
    spmm_fused_kernel<<<NNODE / 8, 256>>>(
        xin[7], xout[7], pAXall + (size_t)7 * NPAD * HID, gammas, 7);

    // serial tail: slab 8 GEMM + bias + log_softmax
    cudaStreamWaitEvent(0, evP1, 0);
    gemm_part_kernel<KCUT2, KTOT, 2><<<GRID_M, 128>>>(pX0, bsort, pYh0, out);
}

// round 16
// speedup vs baseline: 1.0113x; 1.0113x over previous
#include <cuda_runtime.h>
#include <cuda_bf16.h>
#include <cuda_fp16.h>
#include <math.h>
#include <stdint.h>

#define NNODE 100000
#define NPAD  100096          // 782 * 128
#define NEDGE 3200000
#define NFEAT 512
#define HID   256
#define NCLS  64
#define NLAY  8
#define GRID_M 782            // NPAD / 128
#define KTOT  ((NLAY + 1) * HID)   // 2304
#define KCUT1 1280                 // slabs 0..4
#define KCUT2 2048                 // slabs 5..7

// ---------------- static device scratch -------------------------------------
__device__ __align__(16) __half    g_Xbuf0[(size_t)NPAD * HID];  // H (immutable after init)
__device__ __align__(16) __half    g_Xbuf1[(size_t)NPAD * HID];  // ping
__device__ __align__(16) __half    g_Xbuf2[(size_t)NPAD * HID];  // pong
__device__ __align__(16) __half    g_AXall[(size_t)NLAY * NPAD * HID]; // AX_1..8 (slab l-1)
__device__ __align__(16) float     g_Yh0[(size_t)NPAD * NCLS];   // partial Y
__device__ __half g_Wt[HID * NFEAT];               // Winit^T fp16 [n][k]
__device__ __half g_PtAll[NCLS * KTOT];            // fp16 [n][slab*256+k]
__device__ int   g_rowptr[NNODE + 1];
__device__ int   g_cursor[NNODE];
__device__ int2  g_cw[NEDGE];                      // (col, weight bits)
__device__ int   g_bsum[128];
__device__ int   g_boff[128];

static inline int cdiv(int a, int b) { return (a + b - 1) / b; }

__device__ __forceinline__ uint32_t smem_to_u32(const void* p) {
    uint32_t a;
    asm("{ .reg .u64 t; cvta.to.shared.u64 t, %1; cvt.u32.u64 %0, t; }" : "=r"(a) : "l"(p));
    return a;
}

// ---------------- CSR build --------------------------------------------------
__global__ __launch_bounds__(256)
void hist_kernel(const int* __restrict__ erow) {
    int e4 = (blockIdx.x * blockDim.x + threadIdx.x) * 4;
    if (e4 < NEDGE) {
        int4 r = *reinterpret_cast<const int4*>(erow + e4);
        atomicAdd(&g_cursor[r.x], 1);
        atomicAdd(&g_cursor[r.y], 1);
        atomicAdd(&g_cursor[r.z], 1);
        atomicAdd(&g_cursor[r.w], 1);
    }
}
__global__ __launch_bounds__(1024)
void scanA_kernel() {
    __shared__ int sd[1024];
    const int tid = threadIdx.x;
    const int i = blockIdx.x * 1024 + tid;
    int v = (i < NNODE) ? g_cursor[i] : 0;
    sd[tid] = v;
    __syncthreads();
    #pragma unroll
    for (int off = 1; off < 1024; off <<= 1) {
        int t = (tid >= off) ? sd[tid - off] : 0;
        __syncthreads();
        sd[tid] += t;
        __syncthreads();
    }
    if (i < NNODE) g_rowptr[i] = sd[tid] - v;
    if (tid == 1023) g_bsum[blockIdx.x] = sd[1023];
}
__global__ __launch_bounds__(128)
void scanB_kernel(int nblk) {
    __shared__ int sd[128];
    const int tid = threadIdx.x;
    int v = (tid < nblk) ? g_bsum[tid] : 0;
    sd[tid] = v;
    __syncthreads();
    #pragma unroll
    for (int off = 1; off < 128; off <<= 1) {
        int t = (tid >= off) ? sd[tid - off] : 0;
        __syncthreads();
        sd[tid] += t;
        __syncthreads();
    }
    if (tid < nblk) g_boff[tid] = sd[tid] - v;
}
__global__ void scanC_kernel() {
    int i = blockIdx.x * blockDim.x + threadIdx.x;
    if (i < NNODE) {
        int r = g_rowptr[i] + g_boff[i >> 10];
        g_rowptr[i] = r;
        g_cursor[i] = r;
    }
    if (i == 0) g_rowptr[NNODE] = NEDGE;
}
__global__ __launch_bounds__(256)
void scatter_kernel(const int* __restrict__ erow,
                    const int* __restrict__ ecol,
                    const float* __restrict__ ew) {
    int e4 = (blockIdx.x * blockDim.x + threadIdx.x) * 4;
    if (e4 < NEDGE) {
        int4   r = *reinterpret_cast<const int4*>(erow + e4);
        int4   c = *reinterpret_cast<const int4*>(ecol + e4);
        float4 w = *reinterpret_cast<const float4*>(ew + e4);
        int p0 = atomicAdd(&g_cursor[r.x], 1);
        int p1 = atomicAdd(&g_cursor[r.y], 1);
        int p2 = atomicAdd(&g_cursor[r.z], 1);
        int p3 = atomicAdd(&g_cursor[r.w], 1);
        g_cw[p0] = make_int2(c.x, __float_as_int(w.x));
        g_cw[p1] = make_int2(c.y, __float_as_int(w.y));
        g_cw[p2] = make_int2(c.z, __float_as_int(w.z));
        g_cw[p3] = make_int2(c.w, __float_as_int(w.w));
    }
}

// ---------------- weight prep -------------------------------------------------
__global__ void prepWt_kernel(const float* __restrict__ Winit) {
    int i = blockIdx.x * blockDim.x + threadIdx.x;
    if (i < HID * NFEAT) {
        int n = i >> 9, k = i & 511;
        g_Wt[i] = __float2half(Winit[(size_t)k * HID + n]);
    }
}
__global__ void prepWsT_kernel(const float* __restrict__ Wsort) {
    int i = blockIdx.x * blockDim.x + threadIdx.x;
    if (i < NCLS * HID) {
        int n = i >> 8, k = i & 255;
        g_PtAll[(size_t)n * KTOT + k] = __float2half(Wsort[(size_t)k * NCLS + n]);
    }
}
// 32 blocks: block = l*4 + c (one 64-row k-chunk of layer l)
__global__ void prepP_kernel(const float* __restrict__ Ws, const float* __restrict__ Wsort) {
    extern __shared__ float psm[];
    float* sWs = psm;                 // [j][n] 256x64
    float* sW  = psm + HID * NCLS;    // [r][j] 64x256
    const int l = blockIdx.x >> 2;
    const int c = blockIdx.x & 3;
    const int tid = threadIdx.x;
    const float beta = 0.5f / (float)(l + 1);

    for (int i = tid; i < HID * NCLS; i += 256) sWs[i] = Wsort[i];
    for (int i = tid; i < 64 * HID; i += 256)
        sW[i] = Ws[(size_t)l * HID * HID + (size_t)c * 64 * HID + i];
    __syncthreads();

    const int r  = tid & 63;
    const int ng = tid >> 6;
    const int k = c * 64 + r;
    float acc[16];
    #pragma unroll
    for (int j = 0; j < 16; j++) acc[j] = 0.f;
    for (int j2 = 0; j2 < HID; j2++) {
        float w = sW[r * HID + j2];
        #pragma unroll
        for (int j = 0; j < 16; j++)
            acc[j] = fmaf(w, sWs[j2 * NCLS + ng * 16 + j], acc[j]);
    }
    #pragma unroll
    for (int j = 0; j < 16; j++) {
        int n = ng * 16 + j;
        float p = (1.f - beta) * sWs[k * NCLS + n] + beta * acc[j];
        g_PtAll[(size_t)n * KTOT + (size_t)(l + 1) * HID + k] = __float2half(p);
    }
}

// ---------------- HMMA helpers -------------------------------------------------
#define APITCH 40

__device__ __forceinline__ void ldm_x4(uint32_t* d, uint32_t addr) {
    asm volatile("ldmatrix.sync.aligned.m8n8.x4.shared.b16 {%0,%1,%2,%3}, [%4];"
                 : "=r"(d[0]), "=r"(d[1]), "=r"(d[2]), "=r"(d[3]) : "r"(addr));
}
__device__ __forceinline__ void mma16816fp(float* c, const uint32_t* a, const uint32_t* b) {
    asm volatile(
        "mma.sync.aligned.m16n8k16.row.col.f32.f16.f16.f32 "
        "{%0,%1,%2,%3}, {%4,%5,%6,%7}, {%8,%9}, {%0,%1,%2,%3};"
        : "+f"(c[0]), "+f"(c[1]), "+f"(c[2]), "+f"(c[3])
        : "r"(a[0]), "r"(a[1]), "r"(a[2]), "r"(a[3]), "r"(b[0]), "r"(b[1]));
}

// ---------------- init GEMM (software-pipelined): H = X @ Winit + b ----------
#define NCHUNK (NFEAT / 32)   // 16
__global__ __launch_bounds__(256, 2)
void gemm_init_kernel(const float* __restrict__ X,
                      const float* __restrict__ bias,
                      __half* __restrict__ Hout)
{
    __shared__ __align__(16) __half sA[2][128 * APITCH];
    __shared__ __align__(16) __half sB[2][128 * APITCH];

    const int tid = threadIdx.x;
    const int wid = tid >> 5, lid = tid & 31;
    const int row0 = blockIdx.x * 128;
    const int col0 = blockIdx.y * 128;
    const int mwr = (wid >> 1) * 32;
    const int nwb = (wid & 1) * 64;

    const uint32_t sAb = smem_to_u32(sA);
    const uint32_t sBb = smem_to_u32(sB);
    const uint32_t stageBytes = 128 * APITCH * 2;

    const int ar[4] = { (0 * 256 + tid) >> 3, (1 * 256 + tid) >> 3,
                        (2 * 256 + tid) >> 3, (3 * 256 + tid) >> 3 };
    const int as = tid & 7;
    const int br[2] = { (0 * 256 + tid) >> 2, (1 * 256 + tid) >> 2 };
    const int bs = tid & 3;

    float4 fA[4];
    uint4  uB[2];

    auto loadG = [&](int ch) {
        const int kk = ch * 32;
        #pragma unroll
        for (int i = 0; i < 4; i++) {
            int grow = row0 + ar[i];
            fA[i] = (grow < NNODE)
                ? __ldcs(reinterpret_cast<const float4*>(X + (size_t)grow * NFEAT + kk + as * 4))
                : make_float4(0.f, 0.f, 0.f, 0.f);
        }
        #pragma unroll
        for (int i = 0; i < 2; i++)
            uB[i] = *reinterpret_cast<const uint4*>(
                g_Wt + (size_t)(col0 + br[i]) * NFEAT + kk + bs * 8);
    };
    auto storeS = [&](int st) {
        #pragma unroll
        for (int i = 0; i < 4; i++) {
            __half2 h01 = __floats2half2_rn(fA[i].x, fA[i].y);
            __half2 h23 = __floats2half2_rn(fA[i].z, fA[i].w);
            *reinterpret_cast<uint2*>(&sA[st][ar[i] * APITCH + as * 4]) =
                make_uint2(*reinterpret_cast<uint32_t*>(&h01), *reinterpret_cast<uint32_t*>(&h23));
        }
        #pragma unroll
        for (int i = 0; i < 2; i++)
            *reinterpret_cast<uint4*>(&sB[st][br[i] * APITCH + bs * 8]) = uB[i];
    };

    float acc[2][8][4];
    #pragma unroll
    for (int i = 0; i < 2; i++)
        #pragma unroll
        for (int j = 0; j < 8; j++)
            #pragma unroll
            for (int q = 0; q < 4; q++) acc[i][j][q] = 0.f;

    loadG(0);
    storeS(0);
    __syncthreads();

    for (int ch = 0; ch < NCHUNK; ch++) {
        const int cur = ch & 1;
        if (ch + 1 < NCHUNK) loadG(ch + 1);

        #pragma unroll
        for (int ks = 0; ks < 2; ks++) {
            uint32_t a[2][4], b[8][2];
            #pragma unroll
            for (int mi = 0; mi < 2; mi++) {
                uint32_t off = cur * stageBytes +
                    (uint32_t)((mwr + mi * 16 + (lid & 15)) * APITCH
                               + ks * 16 + (lid >> 4) * 8) * 2;
                ldm_x4(a[mi], sAb + off);
            }
            #pragma unroll
            for (int nj = 0; nj < 4; nj++) {
                uint32_t off = cur * stageBytes +
                    (uint32_t)((nwb + nj * 16 + (lid & 7) + ((lid >> 4) & 1) * 8) * APITCH
                               + ks * 16 + ((lid >> 3) & 1) * 8) * 2;
                uint32_t t0[4];
                ldm_x4(t0, sBb + off);
                b[2 * nj][0] = t0[0]; b[2 * nj][1] = t0[1];
                b[2 * nj + 1][0] = t0[2]; b[2 * nj + 1][1] = t0[3];
            }
            #pragma unroll
            for (int mi = 0; mi < 2; mi++)
                #pragma unroll
                for (int nj = 0; nj < 8; nj++)
                    mma16816fp(acc[mi][nj], a[mi], b[nj]);
        }
        __syncthreads();
        if (ch + 1 < NCHUNK) {
            storeS(cur ^ 1);
            __syncthreads();
        }
    }

    const int g = lid >> 2, tg = lid & 3;
    #pragma unroll
    for (int mi = 0; mi < 2; mi++)
        #pragma unroll
        for (int half = 0; half < 2; half++) {
            int row = row0 + mwr + mi * 16 + g + half * 8;
            size_t rb = (size_t)row * HID;
            #pragma unroll
            for (int nj = 0; nj < 8; nj++) {
                int col = nwb + col0 + nj * 8 + tg * 2;
                float v0 = acc[mi][nj][half * 2 + 0] + bias[col];
                float v1 = acc[mi][nj][half * 2 + 1] + bias[col + 1];
                *reinterpret_cast<__half2*>(Hout + rb + col) = __floats2half2_rn(v0, v1);
            }
        }
}

// ---- partial GEMM over K range. slab 0 = H (param), slabs 1..8 = g_AXall.
//      MODE 0: Yh = acc; 1: Yh += acc; 2: out = log_softmax(acc + Yh + bias)
template<int KBEG, int KEND, int MODE>
__global__ __launch_bounds__(128, 4)
void gemm_part_kernel(const __half* __restrict__ H,
                      const float* __restrict__ bias,
                      float* __restrict__ Yh, float* __restrict__ out)
{
    __shared__ __align__(16) __half sA[128 * APITCH];
    __shared__ __align__(16) __half sB[64 * APITCH];

    const int tid = threadIdx.x;
    const int wid = tid >> 5, lid = tid & 31;
    const int row0 = blockIdx.x * 128;
    const int mwr = wid * 32;

    const uint32_t sAb = smem_to_u32(sA);
    const uint32_t sBb = smem_to_u32(sB);

    float acc[2][8][4];
    #pragma unroll
    for (int i = 0; i < 2; i++)
        #pragma unroll
        for (int j = 0; j < 8; j++)
            #pragma unroll
            for (int q = 0; q < 4; q++) acc[i][j][q] = 0.f;

    for (int kk = KBEG; kk < KEND; kk += 32) {
        const int slab = kk >> 8;
        const __half* Ap = (slab == 0) ? H : (g_AXall + (size_t)(slab - 1) * NPAD * HID);
        const int inner = kk & 255;
        #pragma unroll
        for (int i = 0; i < 4; i++) {
            int seg = i * 128 + tid;
            int r = seg >> 2, s = seg & 3;
            uint4 p = __ldcs(reinterpret_cast<const uint4*>(
                Ap + (size_t)(row0 + r) * HID + inner + s * 8));
            *reinterpret_cast<uint4*>(sA + r * APITCH + s * 8) = p;
        }
        #pragma unroll
        for (int i = 0; i < 2; i++) {
            int seg = i * 128 + tid;
            int r = seg >> 2, s = seg & 3;
            uint4 p = *reinterpret_cast<const uint4*>(g_PtAll + (size_t)r * KTOT + kk + s * 8);
            *reinterpret_cast<uint4*>(sB + r * APITCH + s * 8) = p;
        }
        __syncthreads();

        #pragma unroll
        for (int ks = 0; ks < 2; ks++) {
            uint32_t a[2][4], b[8][2];
            #pragma unroll
            for (int mi = 0; mi < 2; mi++) {
                uint32_t off = (uint32_t)((mwr + mi * 16 + (lid & 15)) * APITCH
                                          + ks * 16 + (lid >> 4) * 8) * 2;
                ldm_x4(a[mi], sAb + off);
            }
            #pragma unroll
            for (int nj = 0; nj < 4; nj++) {
                uint32_t off = (uint32_t)((nj * 16 + (lid & 7) + ((lid >> 4) & 1) * 8) * APITCH
                                          + ks * 16 + ((lid >> 3) & 1) * 8) * 2;
                uint32_t t0[4];
                ldm_x4(t0, sBb + off);
                b[2 * nj][0] = t0[0]; b[2 * nj][1] = t0[1];
                b[2 * nj + 1][0] = t0[2]; b[2 * nj + 1][1] = t0[3];
            }
            #pragma unroll
            for (int mi = 0; mi < 2; mi++)
                #pragma unroll
                for (int nj = 0; nj < 8; nj++)
                    mma16816fp(acc[mi][nj], a[mi], b[nj]);
        }
        __syncthreads();
    }

    const int g = lid >> 2, tg = lid & 3;
    if (MODE == 0) {
        #pragma unroll
        for (int mi = 0; mi < 2; mi++)
            #pragma unroll
            for (int half = 0; half < 2; half++) {
                int row = row0 + mwr + mi * 16 + g + half * 8;
                size_t rb = (size_t)row * NCLS;
                #pragma unroll
                for (int nj = 0; nj < 8; nj++) {
                    int col = nj * 8 + tg * 2;
                    *reinterpret_cast<float2*>(Yh + rb + col) =
                        make_float2(acc[mi][nj][half * 2 + 0], acc[mi][nj][half * 2 + 1]);
                }
            }
    } else if (MODE == 1) {
        #pragma unroll
        for (int mi = 0; mi < 2; mi++)
            #pragma unroll
            for (int half = 0; half < 2; half++) {
                int row = row0 + mwr + mi * 16 + g + half * 8;
                size_t rb = (size_t)row * NCLS;
                #pragma unroll
                for (int nj = 0; nj < 8; nj++) {
                    int col = nj * 8 + tg * 2;
                    float2 p = *reinterpret_cast<const float2*>(Yh + rb + col);
                    p.x += acc[mi][nj][half * 2 + 0];
                    p.y += acc[mi][nj][half * 2 + 1];
                    *reinterpret_cast<float2*>(Yh + rb + col) = p;
                }
            }
    } else {
        #pragma unroll
        for (int mi = 0; mi < 2; mi++)
            #pragma unroll
            for (int half = 0; half < 2; half++) {
                int row = row0 + mwr + mi * 16 + g + half * 8;
                size_t rb = (size_t)row * NCLS;
                float v[16];
                float m = -INFINITY;
                #pragma unroll
                for (int nj = 0; nj < 8; nj++) {
                    int col = nj * 8 + tg * 2;
                    float2 p = *reinterpret_cast<const float2*>(Yh + rb + col);
                    v[2 * nj]     = acc[mi][nj][half * 2 + 0] + p.x + bias[col];
                    v[2 * nj + 1] = acc[mi][nj][half * 2 + 1] + p.y + bias[col + 1];
                    m = fmaxf(m, fmaxf(v[2 * nj], v[2 * nj + 1]));
                }
                m = fmaxf(m, __shfl_xor_sync(0xffffffffu, m, 1));
                m = fmaxf(m, __shfl_xor_sync(0xffffffffu, m, 2));
                float s = 0.f;
                #pragma unroll
                for (int j = 0; j < 16; j++) s += expf(v[j] - m);
                s += __shfl_xor_sync(0xffffffffu, s, 1);
                s += __shfl_xor_sync(0xffffffffu, s, 2);
                float lse = m + logf(s);
                if (row < NNODE) {
                    #pragma unroll
                    for (int nj = 0; nj < 8; nj++) {
                        int col = nj * 8 + tg * 2;
                        *reinterpret_cast<float2*>(out + rb + col) =
                            make_float2(v[2 * nj] - lse, v[2 * nj + 1] - lse);
                    }
                }
            }
    }
}

// ---------------- fused SpMM + X-update (fp16 X, warp per row, 8-unroll) ------
// LAST=true: final layer — Xn is never consumed, skip its store.
__device__ __forceinline__ void acc8(float* v, float w, const uint4& x) {
    const __half2* h = reinterpret_cast<const __half2*>(&x);
    #pragma unroll
    for (int j = 0; j < 4; j++) {
        float2 f = __half22float2(h[j]);
        v[2 * j]     = fmaf(w, f.x, v[2 * j]);
        v[2 * j + 1] = fmaf(w, f.y, v[2 * j + 1]);
    }
}

template<bool LAST>
__global__ __launch_bounds__(256)
void spmm_fused_kernel(const __half* __restrict__ Xc, __half* __restrict__ Xn,
                       __half* __restrict__ AXs,
                       const float* __restrict__ gammas, int l)
{
    const int wid  = threadIdx.x >> 5;
    const int lane = threadIdx.x & 31;
    const int row  = blockIdx.x * 8 + wid;
    const int fb   = lane * 8;
    int i = g_rowptr[row];
    const int e = g_rowptr[row + 1];

    float v[8];
    #pragma unroll
    for (int j = 0; j < 8; j++) v[j] = 0.f;

    for (; i + 8 <= e; i += 8) {
        int2 c0 = __ldcs(&g_cw[i + 0]);
        int2 c1 = __ldcs(&g_cw[i + 1]);
        int2 c2 = __ldcs(&g_cw[i + 2]);
        int2 c3 = __ldcs(&g_cw[i + 3]);
        int2 c4 = __ldcs(&g_cw[i + 4]);
        int2 c5 = __ldcs(&g_cw[i + 5]);
        int2 c6 = __ldcs(&g_cw[i + 6]);
        int2 c7 = __ldcs(&g_cw[i + 7]);
        uint4 x0 = __ldg(reinterpret_cast<const uint4*>(Xc + (size_t)c0.x * HID + fb));
        uint4 x1 = __ldg(reinterpret_cast<const uint4*>(Xc + (size_t)c1.x * HID + fb));
        uint4 x2 = __ldg(reinterpret_cast<const uint4*>(Xc + (size_t)c2.x * HID + fb));
        uint4 x3 = __ldg(reinterpret_cast<const uint4*>(Xc + (size_t)c3.x * HID + fb));
        uint4 x4 = __ldg(reinterpret_cast<const uint4*>(Xc + (size_t)c4.x * HID + fb));
        uint4 x5 = __ldg(reinterpret_cast<const uint4*>(Xc + (size_t)c5.x * HID + fb));
        uint4 x6 = __ldg(reinterpret_cast<const uint4*>(Xc + (size_t)c6.x * HID + fb));
        uint4 x7 = __ldg(reinterpret_cast<const uint4*>(Xc + (size_t)c7.x * HID + fb));
        acc8(v, __int_as_float(c0.y), x0);
        acc8(v, __int_as_float(c1.y), x1);
        acc8(v, __int_as_float(c2.y), x2);
        acc8(v, __int_as_float(c3.y), x3);
        acc8(v, __int_as_float(c4.y), x4);
        acc8(v, __int_as_float(c5.y), x5);
        acc8(v, __int_as_float(c6.y), x6);
        acc8(v, __int_as_float(c7.y), x7);
    }
    for (; i + 2 <= e; i += 2) {
        int2 c0 = __ldcs(&g_cw[i + 0]);
        int2 c1 = __ldcs(&g_cw[i + 1]);
        uint4 x0 = __ldg(reinterpret_cast<const uint4*>(Xc + (size_t)c0.x * HID + fb));
        uint4 x1 = __ldg(reinterpret_cast<const uint4*>(Xc + (size_t)c1.x * HID + fb));
        acc8(v, __int_as_float(c0.y), x0);
        acc8(v, __int_as_float(c1.y), x1);
    }
    if (i < e) {
        int2 c0 = __ldcs(&g_cw[i]);
        uint4 x0 = __ldg(reinterpret_cast<const uint4*>(Xc + (size_t)c0.x * HID + fb));
        acc8(v, __int_as_float(c0.y), x0);
    }

    const size_t idx = (size_t)row * HID + fb;
    uint4 ax4;
    __half2* axh = reinterpret_cast<__half2*>(&ax4);
    #pragma unroll
    for (int j = 0; j < 4; j++)
        axh[j] = __floats2half2_rn(v[2 * j], v[2 * j + 1]);

    if (!LAST) {
        const float g = gammas[l];
        uint4 xc4 = *reinterpret_cast<const uint4*>(Xc + idx);
        const __half2* xch = reinterpret_cast<const __half2*>(&xc4);
        uint4 xn4;
        __half2* xnh = reinterpret_cast<__half2*>(&xn4);
        #pragma unroll
        for (int j = 0; j < 4; j++) {
            float2 f = __half22float2(xch[j]);
            xnh[j] = __floats2half2_rn(g * (f.x - v[2 * j]), g * (f.y - v[2 * j + 1]));
        }
        *reinterpret_cast<uint4*>(Xn + idx) = xn4;                   // stay L2-resident
    }
    __stcs(reinterpret_cast<uint4*>(AXs + idx), ax4);                // consumed later
}

// ---------------- launch ------------------------------------------------------
extern "C" void kernel_launch(void* const* d_in, const int* in_sizes, int n_in,
                              void* d_out, int out_size)
{
    const float* X      = (const float*)d_in[0];
    const int*   erow   = (const int*)  d_in[1];
    const int*   ecol   = (const int*)  d_in[2];
    const float* ew     = (const float*)d_in[3];
    const float* Winit  = (const float*)d_in[4];
    const float* binit  = (const float*)d_in[5];
    const float* gammas = (const float*)d_in[6];
    const float* Ws     = (const float*)d_in[7];
    const float* Wsort  = (const float*)d_in[8];
    const float* bsort  = (const float*)d_in[9];
    float* out = (float*)d_out;

    __half *pX0, *pX1, *pX2, *pAXall;
    float *pYh0;
    int *pCursor;
    cudaGetSymbolAddress((void**)&pX0,     g_Xbuf0);
    cudaGetSymbolAddress((void**)&pX1,     g_Xbuf1);
    cudaGetSymbolAddress((void**)&pX2,     g_Xbuf2);
    cudaGetSymbolAddress((void**)&pAXall,  g_AXall);
    cudaGetSymbolAddress((void**)&pYh0,    g_Yh0);
    cudaGetSymbolAddress((void**)&pCursor, g_cursor);

    static int inited = 0;
    static cudaStream_t s2;
    static cudaEvent_t evFork, evJoin, evSlab4, evSlab7, evP1;
    if (!inited) {
        cudaFuncSetAttribute(prepP_kernel,
                             cudaFuncAttributeMaxDynamicSharedMemorySize, 131072);
        cudaStreamCreateWithFlags(&s2, cudaStreamNonBlocking);
        cudaEventCreateWithFlags(&evFork,  cudaEventDisableTiming);
        cudaEventCreateWithFlags(&evJoin,  cudaEventDisableTiming);
        cudaEventCreateWithFlags(&evSlab4, cudaEventDisableTiming);
        cudaEventCreateWithFlags(&evSlab7, cudaEventDisableTiming);
        cudaEventCreateWithFlags(&evP1,    cudaEventDisableTiming);
        inited = 1;
    }

    // ---- fork ----
    cudaEventRecord(evFork, 0);
    cudaStreamWaitEvent(s2, evFork, 0);

    // s2: P-weight prep + CSR build (vectorized)
    prepWsT_kernel<<<cdiv(NCLS * HID, 256), 256, 0, s2>>>(Wsort);
    prepP_kernel<<<NLAY * 4, 256, 131072, s2>>>(Ws, Wsort);
    cudaMemsetAsync(pCursor, 0, NNODE * sizeof(int), s2);
    hist_kernel<<<cdiv(NEDGE / 4, 256), 256, 0, s2>>>(erow);
    scanA_kernel<<<cdiv(NNODE, 1024), 1024, 0, s2>>>();
    scanB_kernel<<<1, 128, 0, s2>>>(cdiv(NNODE, 1024));
    scanC_kernel<<<cdiv(NNODE, 256), 256, 0, s2>>>();
    scatter_kernel<<<cdiv(NEDGE / 4, 256), 256, 0, s2>>>(erow, ecol, ew);
    cudaEventRecord(evJoin, s2);

    // main: Wt prep + init GEMM (H -> Xbuf0 only; kept immutable = slab 0)
    prepWt_kernel<<<cdiv(HID * NFEAT, 256), 256>>>(Winit);
    dim3 ig(GRID_M, 2);
    gemm_init_kernel<<<ig, 256>>>(X, binit, pX0);

    // ---- join: SpMM chain needs CSR + H ----
    cudaStreamWaitEvent(0, evJoin, 0);

    // X rotation: layer 0 reads X0 -> X1; then X1<->X2 alternate.
    __half* xin[NLAY]  = { pX0, pX1, pX2, pX1, pX2, pX1, pX2, pX1 };
    __half* xout[NLAY] = { pX1, pX2, pX1, pX2, pX1, pX2, pX1, pX2 };

    for (int l = 0; l < 4; l++) {
        spmm_fused_kernel<false><<<NNODE / 8, 256>>>(
            xin[l], xout[l], pAXall + (size_t)l * NPAD * HID, gammas, l);
    }
    cudaEventRecord(evSlab4, 0);

    // s2: slabs 0..4 GEMM overlapped with SpMM layers 4..6
    cudaStreamWaitEvent(s2, evSlab4, 0);
    gemm_part_kernel<0, KCUT1, 0><<<GRID_M, 128, 0, s2>>>(pX0, nullptr, pYh0, nullptr);

    for (int l = 4; l < 7; l++) {
        spmm_fused_kernel<false><<<NNODE / 8, 256>>>(
            xin[l], xout[l], pAXall + (size_t)l * NPAD * HID, gammas, l);
    }
    cudaEventRecord(evSlab7, 0);

    // s2: slabs 5..7 GEMM (accumulate) overlapped with SpMM layer 7
    cudaStreamWaitEvent(s2, evSlab7, 0);
    gemm_part_kernel<KCUT1, KCUT2, 1><<<GRID_M, 128, 0, s2>>>(pX0, nullptr, pYh0, nullptr);
    cudaEventRecord(evP1, s2);

    // main: last SpMM layer (no Xn store — X_8 unused)
    spmm_fused_kernel<true><<<NNODE / 8, 256>>>(
        xin[7], xout[7], pAXall + (size_t)7 * NPAD * HID, gammas, 7);

    // serial tail: slab 8 GEMM + bias + log_softmax
    cudaStreamWaitEvent(0, evP1, 0);
    gemm_part_kernel<KCUT2, KTOT, 2><<<GRID_M, 128>>>(pX0, bsort, pYh0, out);
}